// round 3
// baseline (speedup 1.0000x reference)
#include <cuda_runtime.h>
#include <cstdint>

#define Hs 96
#define Is 100
#define Ts 512
#define Bs 512
#define Gs 288               // 3*H
#define Ms (Ts*Bs)           // 262144 rows
#define PH 100               // padded h pitch (floats): 4b-bank spread, 16B aligned

// Scratch for input projections: [dir][m][g]  (604 MB static device array)
__device__ float g_xproj[2][(size_t)Ms * Gs];

typedef unsigned long long u64;

__device__ __forceinline__ u64 fma2(u64 a, u64 b, u64 c) {
    u64 d;
    asm("fma.rn.f32x2 %0, %1, %2, %3;" : "=l"(d) : "l"(a), "l"(b), "l"(c));
    return d;
}
__device__ __forceinline__ float hsum2(u64 a) {
    float x, y;
    asm("mov.b64 {%0,%1}, %2;" : "=f"(x), "=f"(y) : "l"(a));
    return x + y;
}
__device__ __forceinline__ float sigm(float x) {
    return __fdividef(1.0f, 1.0f + __expf(-x));
}
__device__ __forceinline__ float tanh_(float x) {
    // tanh(x) = 1 - 2/(1+e^{2x}); safe at both infinities
    return 1.0f - __fdividef(2.0f, 1.0f + __expf(2.0f * x));
}

// ---------------------------------------------------------------------------
// Input projection: xproj[dir][m][g] = x[m,:] . w_ih[g,:] + b_ih[g]
// Tile: 64 rows x 48 cols, K=100 (50 f32x2 k-pairs). 256 threads, 4x3 per
// thread. Dynamic smem (45.7KB) so 2 CTAs/SM can be resident.
// ---------------------------------------------------------------------------
__global__ __launch_bounds__(256, 2) void proj_kernel(
    const float* __restrict__ x,
    const float* __restrict__ wf, const float* __restrict__ bf,
    const float* __restrict__ wb, const float* __restrict__ bb)
{
    extern __shared__ float psm[];
    float* xs = psm;                 // [64][102]
    float* ws = psm + 64 * 102;      // [48][102]

    const int dir = blockIdx.z;
    const float* __restrict__ w    = dir ? wb : wf;
    const float* __restrict__ bias = dir ? bb : bf;

    const size_t m0 = (size_t)blockIdx.x * 64;
    const int    g0 = blockIdx.y * 48;
    const int tid = threadIdx.x;

    // Coalesced tile loads (source regions are contiguous)
    const float* xsrc = x + m0 * Is;
    for (int i = tid; i < 64 * Is; i += 256) xs[(i / Is) * 102 + (i % Is)] = xsrc[i];
    const float* wsrc = w + (size_t)g0 * Is;
    for (int i = tid; i < 48 * Is; i += 256) ws[(i / Is) * 102 + (i % Is)] = wsrc[i];
    __syncthreads();

    const int cg = tid & 15;   // col group (consecutive tids -> consecutive cols)
    const int rg = tid >> 4;   // row group

    u64 acc[4][3];
    #pragma unroll
    for (int r = 0; r < 4; r++)
        #pragma unroll
        for (int c = 0; c < 3; c++) acc[r][c] = 0ull;

    #pragma unroll 10
    for (int k2 = 0; k2 < 50; k2++) {
        u64 xv[4], wv[3];
        #pragma unroll
        for (int r = 0; r < 4; r++)
            xv[r] = *(const u64*)&xs[(rg * 4 + r) * 102 + 2 * k2];
        #pragma unroll
        for (int c = 0; c < 3; c++)
            wv[c] = *(const u64*)&ws[(cg + 16 * c) * 102 + 2 * k2];
        #pragma unroll
        for (int r = 0; r < 4; r++)
            #pragma unroll
            for (int c = 0; c < 3; c++)
                acc[r][c] = fma2(xv[r], wv[c], acc[r][c]);
    }

    #pragma unroll
    for (int c = 0; c < 3; c++) {
        const int gcol = g0 + cg + 16 * c;
        const float bv = __ldg(&bias[gcol]);
        #pragma unroll
        for (int r = 0; r < 4; r++) {
            const size_t m = m0 + rg * 4 + r;
            g_xproj[dir][m * Gs + gcol] = hsum2(acc[r][c]) + bv;
        }
    }
}

// ---------------------------------------------------------------------------
// Recurrent scan: 128 CTAs (64 batch-groups x 2 dirs), 768 threads = 24 warps
// (6 per SMSP, balanced). Thread (b,i): tid = i*8 + b. Each thread computes
// the r, z, n dot products for its own (batch b, hidden index i) -> gates are
// evaluated in place (no smem exchange), h held in a register, double-buffered
// h in smem -> ONE barrier per step.
// W_hh lives in smem (110KB): warp reads touch 4 row-addresses (8-way
// broadcast) -> conflict-free. h reads: 8 addresses spread by PH=100 pitch
// -> conflict-free. h chunk is reused across the 3 gate rows (LDS 96/thread
// vs FMA2 144/thread).
// ---------------------------------------------------------------------------
__global__ __launch_bounds__(768, 1) void scan_kernel(
    const float* __restrict__ whf, const float* __restrict__ bhf,
    const float* __restrict__ whb, const float* __restrict__ bhb,
    float* __restrict__ out)
{
    extern __shared__ float sm[];
    float* w_s  = sm;                    // [288*96]
    float* hbuf = sm + Gs * Hs;          // [2][8][PH]

    const int tid = threadIdx.x;
    const int i = tid >> 3;              // 0..95 hidden index
    const int b = tid & 7;               // 0..7  batch-in-group
    const int dir = blockIdx.x >> 6;
    const int b0  = (blockIdx.x & 63) * 8;

    const float* __restrict__ wh = dir ? whb : whf;
    const float* __restrict__ bh = dir ? bhb : bhf;

    // Stage W_hh into smem (row-major [288][96]), zero both h buffers
    for (int j = tid; j < Gs * Hs; j += 768) w_s[j] = wh[j];
    for (int j = tid; j < 2 * 8 * PH; j += 768) hbuf[j] = 0.0f;

    const float bh_r = __ldg(&bh[i]);
    const float bh_z = __ldg(&bh[Hs + i]);
    const float bh_n = __ldg(&bh[2 * Hs + i]);

    const float* __restrict__ xpb = g_xproj[dir];
    const int t_first = dir ? (Ts - 1) : 0;
    const int tstep   = dir ? -1 : 1;

    const float* wr0 = w_s + i * Hs;              // row i        (r gate)
    const float* wr1 = w_s + (Hs + i) * Hs;       // row 96+i     (z gate)
    const float* wr2 = w_s + (2 * Hs + i) * Hs;   // row 192+i    (n gate)

    float hreg = 0.0f;
    int tt = t_first;
    size_t xoff = ((size_t)tt * Bs + b0 + b) * Gs + i;
    float xc_r = __ldg(&xpb[xoff]);
    float xc_z = __ldg(&xpb[xoff + Hs]);
    float xc_n = __ldg(&xpb[xoff + 2 * Hs]);

    __syncthreads();

    int p = 0;
    #pragma unroll 1
    for (int t = 0; t < Ts; t++) {
        // Prefetch next step's xp (consumed after the barrier next iteration)
        const int tn = (t == Ts - 1) ? tt : (tt + tstep);
        const size_t xoff2 = ((size_t)tn * Bs + b0 + b) * Gs + i;
        const float xn_r = __ldg(&xpb[xoff2]);
        const float xn_z = __ldg(&xpb[xoff2 + Hs]);
        const float xn_n = __ldg(&xpb[xoff2 + 2 * Hs]);

        // Matvec: hp_g = W_hh[g,:] . h[b]  for g = i, 96+i, 192+i
        const float* hb = hbuf + p * (8 * PH) + b * PH;
        u64 a0 = 0, a1 = 0, a2 = 0, a3 = 0, a4 = 0, a5 = 0;
        #pragma unroll
        for (int c = 0; c < 24; c += 2) {
            const ulonglong2 h0 = *(const ulonglong2*)(hb + 4 * c);
            const ulonglong2 h1 = *(const ulonglong2*)(hb + 4 * c + 4);
            const ulonglong2 w0 = *(const ulonglong2*)(wr0 + 4 * c);
            const ulonglong2 w0b = *(const ulonglong2*)(wr0 + 4 * c + 4);
            a0 = fma2(w0.x,  h0.x, a0);  a0 = fma2(w0.y,  h0.y, a0);
            a3 = fma2(w0b.x, h1.x, a3);  a3 = fma2(w0b.y, h1.y, a3);
            const ulonglong2 w1 = *(const ulonglong2*)(wr1 + 4 * c);
            const ulonglong2 w1b = *(const ulonglong2*)(wr1 + 4 * c + 4);
            a1 = fma2(w1.x,  h0.x, a1);  a1 = fma2(w1.y,  h0.y, a1);
            a4 = fma2(w1b.x, h1.x, a4);  a4 = fma2(w1b.y, h1.y, a4);
            const ulonglong2 w2v = *(const ulonglong2*)(wr2 + 4 * c);
            const ulonglong2 w2b = *(const ulonglong2*)(wr2 + 4 * c + 4);
            a2 = fma2(w2v.x, h0.x, a2);  a2 = fma2(w2v.y, h0.y, a2);
            a5 = fma2(w2b.x, h1.x, a5);  a5 = fma2(w2b.y, h1.y, a5);
        }
        const float hp_r = hsum2(a0) + hsum2(a3) + bh_r;
        const float hp_z = hsum2(a1) + hsum2(a4) + bh_z;
        const float hp_n = hsum2(a2) + hsum2(a5) + bh_n;

        // Gates (in place, no exchange)
        const float r = sigm(xc_r + hp_r);
        const float z = sigm(xc_z + hp_z);
        const float n = tanh_(fmaf(r, hp_n, xc_n));
        const float hnew = fmaf(z, hreg - n, n);
        hreg = hnew;

        hbuf[(1 - p) * (8 * PH) + b * PH + i] = hnew;
        out[((size_t)tt * Bs + b0 + b) * (2 * Hs) + dir * Hs + i] = hnew;

        __syncthreads();
        p ^= 1;
        xc_r = xn_r; xc_z = xn_z; xc_n = xn_n;
        tt = tn;
    }
}

// ---------------------------------------------------------------------------
extern "C" void kernel_launch(void* const* d_in, const int* in_sizes, int n_in,
                              void* d_out, int out_size)
{
    const float* x      = (const float*)d_in[0];
    const float* w_ih_f = (const float*)d_in[1];
    const float* w_hh_f = (const float*)d_in[2];
    const float* b_ih_f = (const float*)d_in[3];
    const float* b_hh_f = (const float*)d_in[4];
    const float* w_ih_b = (const float*)d_in[5];
    const float* w_hh_b = (const float*)d_in[6];
    const float* b_ih_b = (const float*)d_in[7];
    const float* b_hh_b = (const float*)d_in[8];
    float* out = (float*)d_out;

    const int proj_smem = (64 * 102 + 48 * 102) * sizeof(float);     // 45696 B
    const int scan_smem = (Gs * Hs + 2 * 8 * PH) * sizeof(float);    // 116992 B

    static bool attr_done = false;
    if (!attr_done) {
        cudaFuncSetAttribute(scan_kernel,
                             cudaFuncAttributeMaxDynamicSharedMemorySize, scan_smem);
        cudaFuncSetAttribute(proj_kernel,
                             cudaFuncAttributeMaxDynamicSharedMemorySize, proj_smem);
        attr_done = true;
    }

    dim3 pg(Ms / 64, Gs / 48, 2);     // (4096, 6, 2)
    proj_kernel<<<pg, 256, proj_smem>>>(x, w_ih_f, b_ih_f, w_ih_b, b_ih_b);
    scan_kernel<<<128, 768, scan_smem>>>(w_hh_f, b_hh_f, w_hh_b, b_hh_b, out);
}

// round 6
// speedup vs baseline: 1.6915x; 1.6915x over previous
#include <cuda_runtime.h>
#include <cstdint>

#define Hs 96
#define Is 100
#define Ts 512
#define Bs 512
#define Gs 288               // 3*H
#define Ms (Ts*Bs)           // 262144 rows

// Scratch for input projections: [dir][m][g]
__device__ float g_xproj[2][(size_t)Ms * Gs];

typedef unsigned long long u64;

__device__ __forceinline__ u64 fma2(u64 a, u64 b, u64 c) {
    u64 d;
    asm("fma.rn.f32x2 %0, %1, %2, %3;" : "=l"(d) : "l"(a), "l"(b), "l"(c));
    return d;
}
__device__ __forceinline__ float hsum2(u64 a) {
    float x, y;
    asm("mov.b64 {%0,%1}, %2;" : "=f"(x), "=f"(y) : "l"(a));
    return x + y;
}
__device__ __forceinline__ float sigm(float x) {
    return __fdividef(1.0f, 1.0f + __expf(-x));
}
__device__ __forceinline__ float tanh_(float x) {
    return 1.0f - __fdividef(2.0f, 1.0f + __expf(2.0f * x));
}

// ---------------------------------------------------------------------------
// Input projection. Tile 64 m-rows x 48 g-cols, K=100.
// grid = (12, 4096): blockIdx.x = gtile+6*dir (fastest) so the 12 CTAs that
// share an x-tile are schedule-adjacent -> x read once from DRAM, 11x from L2.
// Inner loop: 128-bit smem loads, k-chunks of 4 -> 7 LDS.128 per 24 fma2.
// occ=3 (24 warps/SM) for latency hiding.
// ---------------------------------------------------------------------------
__global__ __launch_bounds__(256, 3) void proj_kernel(
    const float* __restrict__ x,
    const float* __restrict__ wf, const float* __restrict__ bf,
    const float* __restrict__ wb, const float* __restrict__ bb)
{
    __shared__ __align__(16) float xs[64 * Is];   // pitch 100 (400B, 16B-aligned)
    __shared__ __align__(16) float ws[48 * Is];

    const int bx = blockIdx.x;
    const int dir = (bx >= 6);
    const int g0 = (dir ? bx - 6 : bx) * 48;
    const size_t m0 = (size_t)blockIdx.y * 64;
    const int tid = threadIdx.x;

    const float* __restrict__ w    = dir ? wb : wf;
    const float* __restrict__ bias = dir ? bb : bf;

    // Vectorized tile loads (both source regions contiguous + 16B aligned)
    {
        const float4* xsrc = (const float4*)(x + m0 * Is);
        float4* xd = (float4*)xs;
        for (int i = tid; i < 64 * Is / 4; i += 256) xd[i] = xsrc[i];
        const float4* wsrc = (const float4*)(w + (size_t)g0 * Is);
        float4* wd = (float4*)ws;
        for (int i = tid; i < 48 * Is / 4; i += 256) wd[i] = wsrc[i];
    }
    __syncthreads();

    const int cg = tid & 15;   // col group
    const int rg = tid >> 4;   // row group

    u64 acc[4][3];
    #pragma unroll
    for (int r = 0; r < 4; r++)
        #pragma unroll
        for (int c = 0; c < 3; c++) acc[r][c] = 0ull;

    #pragma unroll 5
    for (int k4 = 0; k4 < 25; k4++) {           // 4 k-values per iter
        ulonglong2 xv[4], wv[3];
        #pragma unroll
        for (int r = 0; r < 4; r++)
            xv[r] = *(const ulonglong2*)&xs[(rg * 4 + r) * Is + 4 * k4];
        #pragma unroll
        for (int c = 0; c < 3; c++)
            wv[c] = *(const ulonglong2*)&ws[(cg + 16 * c) * Is + 4 * k4];
        #pragma unroll
        for (int r = 0; r < 4; r++)
            #pragma unroll
            for (int c = 0; c < 3; c++) {
                acc[r][c] = fma2(xv[r].x, wv[c].x, acc[r][c]);
                acc[r][c] = fma2(xv[r].y, wv[c].y, acc[r][c]);
            }
    }

    #pragma unroll
    for (int c = 0; c < 3; c++) {
        const int gcol = g0 + cg + 16 * c;
        const float bv = __ldg(&bias[gcol]);
        #pragma unroll
        for (int r = 0; r < 4; r++) {
            const size_t m = m0 + rg * 4 + r;
            g_xproj[dir][m * Gs + gcol] = hsum2(acc[r][c]) + bv;
        }
    }
}

// ---------------------------------------------------------------------------
// Recurrent scan. 128 CTAs (64 batch-groups x 2 dirs), 288 threads = 9 warps.
// Thread g owns W_hh row g in 48 u64 REGISTERS (rule: per-thread data in regs).
// h lives in smem and is read with warp-UNIFORM addresses (true broadcast,
// deduped wavefronts). Per step:
//   stage1: hp[g] = W[g,:].h[b] for 8 batches (8 indep fma2 chains)
//   stage2: r-rows (g<96) and z-rows (96<=g<192) apply sigmoid THEMSELVES and
//           publish only the activated scalar; n-rows keep hp_n/xp_n in regs.
//   barrier; stage3: n-row threads (3 warps) finalize tanh + state update.
//   barrier.
// ---------------------------------------------------------------------------
__global__ __launch_bounds__(288, 1) void scan_kernel(
    const float* __restrict__ whf, const float* __restrict__ bhf,
    const float* __restrict__ whb, const float* __restrict__ bhb,
    float* __restrict__ out)
{
    __shared__ __align__(16) float hsh[8][Hs];   // hidden state
    __shared__ float rz[8][2 * Hs];              // activated r (0..95), z (96..191)

    const int tid = threadIdx.x;                 // gate row g
    const int dir = blockIdx.x >> 6;
    const int b0  = (blockIdx.x & 63) * 8;

    const float* __restrict__ wh = dir ? whb : whf;
    const float* __restrict__ bh = dir ? bhb : bhf;

    // W_hh row -> registers
    u64 w2[48];
    {
        const u64* wrow = (const u64*)(wh + tid * Hs);
        #pragma unroll
        for (int j = 0; j < 48; j++) w2[j] = __ldg(&wrow[j]);
    }
    const float bhv = __ldg(&bh[tid]);

    for (int i = tid; i < 8 * Hs; i += 288) (&hsh[0][0])[i] = 0.0f;

    const float* __restrict__ xpb = g_xproj[dir];
    const int t_first = dir ? (Ts - 1) : 0;
    const int tstep   = dir ? -1 : 1;

    const bool is_n = (tid >= 2 * Hs);
    const int  in   = tid - 2 * Hs;              // n-row hidden index (valid if is_n)

    float xc[8], xn[8];
    #pragma unroll
    for (int bb = 0; bb < 8; bb++)
        xc[bb] = __ldg(&xpb[((size_t)t_first * Bs + b0 + bb) * Gs + tid]);

    __syncthreads();

    int tt = t_first;
    #pragma unroll 1
    for (int t = 0; t < Ts; t++) {
        // Prefetch next step's xp
        const int tn = (t == Ts - 1) ? tt : (tt + tstep);
        #pragma unroll
        for (int bb = 0; bb < 8; bb++)
            xn[bb] = __ldg(&xpb[((size_t)tn * Bs + b0 + bb) * Gs + tid]);

        // Stage 1: matvec, 8 independent accumulator chains, uniform h loads
        u64 acc[8];
        #pragma unroll
        for (int bb = 0; bb < 8; bb++) acc[bb] = 0ull;
        #pragma unroll
        for (int j = 0; j < 24; j++) {
            ulonglong2 hv[8];
            #pragma unroll
            for (int bb = 0; bb < 8; bb++)
                hv[bb] = *(const ulonglong2*)&hsh[bb][4 * j];   // uniform broadcast
            #pragma unroll
            for (int bb = 0; bb < 8; bb++) {
                acc[bb] = fma2(w2[2 * j],     hv[bb].x, acc[bb]);
                acc[bb] = fma2(w2[2 * j + 1], hv[bb].y, acc[bb]);
            }
        }

        // Stage 2: activate own gate where possible
        float hpn[8];
        if (!is_n) {
            #pragma unroll
            for (int bb = 0; bb < 8; bb++) {
                const float a = sigm(xc[bb] + hsum2(acc[bb]) + bhv);
                rz[bb][tid] = a;                 // r in [0,96), z in [96,192)
            }
        } else {
            #pragma unroll
            for (int bb = 0; bb < 8; bb++)
                hpn[bb] = hsum2(acc[bb]) + bhv;  // keep in registers
        }
        __syncthreads();

        // Stage 3: n-row threads (96 threads, warps 6-8) finalize
        if (is_n) {
            #pragma unroll
            for (int bb = 0; bb < 8; bb++) {
                const float r = rz[bb][in];
                const float z = rz[bb][Hs + in];
                const float n = tanh_(fmaf(r, hpn[bb], xc[bb]));
                const float hold = hsh[bb][in];
                const float hnew = fmaf(z, hold - n, n);
                hsh[bb][in] = hnew;
                out[((size_t)tt * Bs + b0 + bb) * (2 * Hs) + dir * Hs + in] = hnew;
            }
        }
        __syncthreads();

        #pragma unroll
        for (int bb = 0; bb < 8; bb++) xc[bb] = xn[bb];
        tt = tn;
    }
}

// ---------------------------------------------------------------------------
extern "C" void kernel_launch(void* const* d_in, const int* in_sizes, int n_in,
                              void* d_out, int out_size)
{
    const float* x      = (const float*)d_in[0];
    const float* w_ih_f = (const float*)d_in[1];
    const float* w_hh_f = (const float*)d_in[2];
    const float* b_ih_f = (const float*)d_in[3];
    const float* b_hh_f = (const float*)d_in[4];
    const float* w_ih_b = (const float*)d_in[5];
    const float* w_hh_b = (const float*)d_in[6];
    const float* b_ih_b = (const float*)d_in[7];
    const float* b_hh_b = (const float*)d_in[8];
    float* out = (float*)d_out;

    dim3 pg(12, Ms / 64);     // gtile*dir fastest -> L2 reuse of x tiles
    proj_kernel<<<pg, 256>>>(x, w_ih_f, b_ih_f, w_ih_b, b_ih_b);
    scan_kernel<<<128, 288>>>(w_hh_f, b_hh_f, w_hh_b, b_hh_b, out);
}